// round 5
// baseline (speedup 1.0000x reference)
#include <cuda_runtime.h>
#include <stdint.h>

// ---------------------------------------------------------------------------
// ExtractGraph: maxpool2x2 -> +uniform noise -> diagonal-stencil adjacency
// (transposed) -> bernoulli(0.5) dropout.
// Output: FLOAT32 (harness converts the bool reference to float32; supported
// dtypes are float32/int32/bf16 only).
// RNG = JAX threefry2x32, partitionable scheme (default since JAX 0.4.36):
//   split(key)[i]      = both output words of threefry(key, (0, i))
//   random_bits(32)[t] = o0 ^ o1 of threefry(key, (hi(t), lo(t)))
// ---------------------------------------------------------------------------

#define PM 2048
#define PN 2048

static __device__ float    g_dnT[(size_t)PM * PN];   // d_noised TRANSPOSED: g_dnT[j][i]
static __device__ unsigned g_min_u;
static __device__ unsigned g_max_u;

__host__ __device__ __forceinline__ uint32_t rotl32(uint32_t x, int d) {
    return (x << d) | (x >> (32 - d));
}

// Threefry-2x32, 20 rounds, exactly as in jax/_src/prng.py.
__host__ __device__ __forceinline__ void tf2x32(uint32_t k0, uint32_t k1,
                                                uint32_t c0, uint32_t c1,
                                                uint32_t& o0, uint32_t& o1) {
    uint32_t ks2 = k0 ^ k1 ^ 0x1BD11BDAu;
    uint32_t x0 = c0 + k0;
    uint32_t x1 = c1 + k1;
#define TFR(R) { x0 += x1; x1 = rotl32(x1, R); x1 ^= x0; }
    TFR(13) TFR(15) TFR(26) TFR(6)
    x0 += k1;  x1 += ks2 + 1u;
    TFR(17) TFR(29) TFR(16) TFR(24)
    x0 += ks2; x1 += k0 + 2u;
    TFR(13) TFR(15) TFR(26) TFR(6)
    x0 += k0;  x1 += k1 + 3u;
    TFR(17) TFR(29) TFR(16) TFR(24)
    x0 += k1;  x1 += ks2 + 4u;
    TFR(13) TFR(15) TFR(26) TFR(6)
    x0 += ks2; x1 += k0 + 5u;
#undef TFR
    o0 = x0; o1 = x1;
}

// Partitionable 32-bit random bits: XOR of both cipher words.
__device__ __forceinline__ uint32_t tf_bits32(uint32_t k0, uint32_t k1,
                                              uint32_t c0, uint32_t c1) {
    uint32_t o0, o1;
    tf2x32(k0, k1, c0, c1, o0, o1);
    return o0 ^ o1;
}

// JAX uniform(0,1) float32 from 32 random bits.
__device__ __forceinline__ float u01(uint32_t b) {
    return __uint_as_float((b >> 9) | 0x3f800000u) - 1.0f;
}

// Order-preserving float<->uint mapping for atomic min/max (no NaNs in input).
__device__ __forceinline__ unsigned f2sortable(float f) {
    unsigned u = __float_as_uint(f);
    return (u & 0x80000000u) ? ~u : (u | 0x80000000u);
}
__device__ __forceinline__ float sortable2f(unsigned u) {
    unsigned b = (u & 0x80000000u) ? (u ^ 0x80000000u) : ~u;
    return __uint_as_float(b);
}

__global__ void init_minmax_kernel() {
    g_min_u = 0xFFFFFFFFu;
    g_max_u = 0u;
}

// Kernel A: maxpool 2x2 + threefry noise, write d_noised transposed via smem
// tile; block-reduce min/max of d_pool into global atomics.
// Block (32,8), each thread 4 pool elements; block tile = 32x32 pool elems.
__global__ void __launch_bounds__(256) pool_noise_kernel(
    const float* __restrict__ dc, uint32_t kn0, uint32_t kn1) {
    __shared__ float s[32][33];
    const int tx = threadIdx.x, ty = threadIdx.y;
    const int j0 = blockIdx.x * 32;      // pool col tile
    const int i0 = blockIdx.y * 32;      // pool row tile
    const int j  = j0 + tx;

    unsigned lmin = 0xFFFFFFFFu, lmax = 0u;

#pragma unroll
    for (int k = 0; k < 4; ++k) {
        const int i = i0 + ty + 8 * k;
        const float2* row0 = reinterpret_cast<const float2*>(dc + (size_t)(2 * i) * 4096);
        const float2* row1 = reinterpret_cast<const float2*>(dc + (size_t)(2 * i + 1) * 4096);
        const float2 a = __ldg(&row0[j]);
        const float2 b = __ldg(&row1[j]);
        const float p = fmaxf(fmaxf(a.x, a.y), fmaxf(b.x, b.y));

        const unsigned e = f2sortable(p);
        lmin = min(lmin, e);
        lmax = max(lmax, e);

        const uint32_t bits = tf_bits32(kn0, kn1, 0u, (uint32_t)(i * PN + j));
        s[tx][ty + 8 * k] = p + u01(bits);
    }
    __syncthreads();

    // transposed, coalesced write: g_dnT[j][i]
#pragma unroll
    for (int k = 0; k < 4; ++k) {
        const int lj = ty + 8 * k;
        g_dnT[(size_t)(j0 + lj) * PM + i0 + tx] = s[lj][tx];
    }

    // block min/max reduction (blockDim.x==32 => ty is the warp id)
    lmin = __reduce_min_sync(0xffffffffu, lmin);
    lmax = __reduce_max_sync(0xffffffffu, lmax);
    __shared__ unsigned rmin[8], rmax[8];
    if (tx == 0) { rmin[ty] = lmin; rmax[ty] = lmax; }
    __syncthreads();
    if (ty == 0 && tx == 0) {
        unsigned m0 = rmin[0], m1 = rmax[0];
#pragma unroll
        for (int w = 1; w < 8; ++w) { m0 = min(m0, rmin[w]); m1 = max(m1, rmax[w]); }
        atomicMin(&g_min_u, m0);
        atomicMax(&g_max_u, m1);
    }
}

// Kernel B: out[r][c] (FLOAT) = keep(r,c) & OR_{dx,dy in +-1} mask(i=c,j=r) &
//                               |dn[c+dy][r+dx] - dn[c][r]| <= thr
// with dn accessed through its transpose g_dnT (coalesced loads).
__global__ void __launch_bounds__(256) graph_kernel(
    float* __restrict__ out, uint32_t kd0, uint32_t kd1) {
    const int c = blockIdx.x * 32 + threadIdx.x;
    const int r = blockIdx.y * 8 + threadIdx.y;

    const float thr = (sortable2f(g_max_u) - sortable2f(g_min_u)) / 2048.0f;

    const float center = g_dnT[(size_t)r * PM + c];
    bool adj = false;
#pragma unroll
    for (int dx = -1; dx <= 1; dx += 2) {
#pragma unroll
        for (int dy = -1; dy <= 1; dy += 2) {
            // reference mask at (i=c, j=r), all six original conditions:
            const bool m = (c + dx >= 0) && (c + dy < PM) && (r + dx >= 0) &&
                           (r + dy < PN) && (c + dy >= 0) && (r + dx < PN);
            if (m) {
                const float v = g_dnT[(size_t)(r + dx) * PM + (c + dy)];
                adj |= (fabsf(v - center) <= thr);
            }
        }
    }

    const uint32_t idx = (uint32_t)(r * PN + c);
    const bool keep = u01(tf_bits32(kd0, kd1, 0u, idx)) < 0.5f;

    out[idx] = (adj && keep) ? 1.0f : 0.0f;
}

extern "C" void kernel_launch(void* const* d_in, const int* in_sizes, int n_in,
                              void* d_out, int out_size) {
    (void)in_sizes; (void)n_in; (void)out_size;
    const float* dc = (const float*)d_in[0];
    float* out = (float*)d_out;

    // jax.random.key(1) -> (0,1). Partitionable split:
    //   k_noise = words of threefry((0,1), (0,0))
    //   k_drop  = words of threefry((0,1), (0,1))
    uint32_t kn0, kn1, kd0, kd1;
    tf2x32(0u, 1u, 0u, 0u, kn0, kn1);
    tf2x32(0u, 1u, 0u, 1u, kd0, kd1);

    init_minmax_kernel<<<1, 1>>>();
    pool_noise_kernel<<<dim3(64, 64), dim3(32, 8)>>>(dc, kn0, kn1);
    graph_kernel<<<dim3(64, 256), dim3(32, 8)>>>(out, kd0, kd1);
}